// round 3
// baseline (speedup 1.0000x reference)
#include <cuda_runtime.h>

// out = relu(cos(x+theta) @ W1 + b1) @ W2 + b2
// x: [B*S, 8] fp32, W1: [8,32], W2: [32,8], out: [B*S, 8] fp32
//
// f32x2-packed (2 rows per vector lane, 2 pairs = 4 rows/thread) with
// layer1/layer2 FUSED per hidden column j so only one h value is live at a
// time (kills the 128-reg h[][] footprint of the previous version).
// Weights pre-broadcast to {w,w} u64 pairs in shared, TRANSPOSED so each
// column j's weights are contiguous -> LDS.128 feeds 2 FFMA2s.

using u64 = unsigned long long;

__device__ __forceinline__ u64 pack2(float lo, float hi) {
    u64 r;
    asm("mov.b64 %0, {%1, %2};" : "=l"(r) : "f"(lo), "f"(hi));
    return r;
}

__device__ __forceinline__ float2 unpack2(u64 v) {
    float2 f;
    asm("mov.b64 {%0, %1}, %2;" : "=f"(f.x), "=f"(f.y) : "l"(v));
    return f;
}

__device__ __forceinline__ u64 ffma2(u64 a, u64 b, u64 c) {
    u64 d;
    asm("fma.rn.f32x2 %0, %1, %2, %3;" : "=l"(d) : "l"(a), "l"(b), "l"(c));
    return d;
}

__device__ __forceinline__ u64 relu2(u64 v) {
    float2 f = unpack2(v);              // register-pair halves: no data movement
    f.x = fmaxf(f.x, 0.0f);             // FMNMX (alu pipe)
    f.y = fmaxf(f.y, 0.0f);
    return pack2(f.x, f.y);
}

constexpr int E = 8;
constexpr int F = 32;
constexpr int PAIRS = 2;                   // f32x2 row-pairs per thread
constexpr int ROWS_PER_THREAD = 2 * PAIRS; // 4 rows/thread
constexpr int BLOCK = 128;

__global__ __launch_bounds__(BLOCK)
void ffq_kernel(const float* __restrict__ x,
                const float* __restrict__ theta,
                const float* __restrict__ w1,
                const float* __restrict__ b1,
                const float* __restrict__ w2,
                const float* __restrict__ b2,
                float* __restrict__ out,
                long nrows)
{
    // Transposed, broadcast-packed weights:
    //   s_w1t[j*E + i] = {w1[i][j], w1[i][j]}   (column j contiguous, 16B-aligned)
    //   s_w2 [j*E + e] = {w2[j][e], w2[j][e]}   (already row-contiguous)
    __shared__ __align__(16) u64 s_w1t[F * E];
    __shared__ __align__(16) u64 s_w2 [F * E];
    __shared__ __align__(16) u64 s_b1 [F];
    __shared__ __align__(16) u64 s_b2 [E];
    __shared__ float s_th[E];

    const int t = threadIdx.x;

    for (int k = t; k < F * E; k += BLOCK) {
        int j = k / E, i = k % E;
        float a = w1[i * F + j];
        s_w1t[k] = pack2(a, a);
        float b = w2[k];                  // w2 is [F][E], k = j*E+e already
        s_w2[k] = pack2(b, b);
    }
    if (t < F) { float v = b1[t]; s_b1[t] = pack2(v, v); }
    if (t < E) {
        float v = b2[t]; s_b2[t] = pack2(v, v);
        s_th[t] = theta[t];
    }
    __syncthreads();

    const long row0 = ((long)blockIdx.x * BLOCK + t) * ROWS_PER_THREAD;
    if (row0 >= nrows) return;

    float th[E];
#pragma unroll
    for (int i = 0; i < E; i++) th[i] = s_th[i];

    // ---- Load x rows (4 rows x 8 floats = 8x LDG.128)
    const float4* xv = (const float4*)(x + row0 * E);
    float xr[ROWS_PER_THREAD][E];
#pragma unroll
    for (int r = 0; r < ROWS_PER_THREAD; r++) {
        float4 lo = xv[2 * r + 0];
        float4 hi = xv[2 * r + 1];
        xr[r][0] = lo.x; xr[r][1] = lo.y; xr[r][2] = lo.z; xr[r][3] = lo.w;
        xr[r][4] = hi.x; xr[r][5] = hi.y; xr[r][6] = hi.z; xr[r][7] = hi.w;
    }

    // ---- q = cos(x + theta), packed as {row 2p, row 2p+1}
    u64 q[PAIRS][E];
#pragma unroll
    for (int p = 0; p < PAIRS; p++) {
#pragma unroll
        for (int i = 0; i < E; i++) {
            float a = __cosf(xr[2 * p + 0][i] + th[i]);
            float b = __cosf(xr[2 * p + 1][i] + th[i]);
            q[p][i] = pack2(a, b);
        }
    }

    // ---- Fused layers: o_e = b2_e + sum_j relu(q . w1[:,j] + b1_j) * w2[j,e]
    u64 o[PAIRS][E];
#pragma unroll
    for (int e = 0; e < E; e++) {
        u64 be = s_b2[e];
        o[0][e] = be;
        o[1][e] = be;
    }

#pragma unroll 4
    for (int j = 0; j < F; j++) {
        u64 bj = s_b1[j];
        u64 h0 = bj, h1 = bj;
        const u64* wc = &s_w1t[j * E];
#pragma unroll
        for (int i = 0; i < E; i++) {
            u64 w = wc[i];
            h0 = ffma2(q[0][i], w, h0);
            h1 = ffma2(q[1][i], w, h1);
        }
        h0 = relu2(h0);
        h1 = relu2(h1);
        const u64* wr = &s_w2[j * E];
#pragma unroll
        for (int e = 0; e < E; e++) {
            u64 w = wr[e];
            o[0][e] = ffma2(h0, w, o[0][e]);
            o[1][e] = ffma2(h1, w, o[1][e]);
        }
    }

    // ---- Store 4 rows (8x STG.128): row 2p = lo halves, row 2p+1 = hi halves
    float4* ov = (float4*)(out + row0 * E);
#pragma unroll
    for (int p = 0; p < PAIRS; p++) {
        float2 f[E];
#pragma unroll
        for (int e = 0; e < E; e++) f[e] = unpack2(o[p][e]);
        ov[4 * p + 0] = make_float4(f[0].x, f[1].x, f[2].x, f[3].x);
        ov[4 * p + 1] = make_float4(f[4].x, f[5].x, f[6].x, f[7].x);
        ov[4 * p + 2] = make_float4(f[0].y, f[1].y, f[2].y, f[3].y);
        ov[4 * p + 3] = make_float4(f[4].y, f[5].y, f[6].y, f[7].y);
    }
}

extern "C" void kernel_launch(void* const* d_in, const int* in_sizes, int n_in,
                              void* d_out, int out_size)
{
    const float* x     = (const float*)d_in[0];
    const float* theta = (const float*)d_in[1];
    const float* w1    = (const float*)d_in[2];
    const float* b1    = (const float*)d_in[3];
    const float* w2    = (const float*)d_in[4];
    const float* b2    = (const float*)d_in[5];
    float* out = (float*)d_out;

    const long nrows = (long)in_sizes[0] / E;  // 524288
    const long nthreads = (nrows + ROWS_PER_THREAD - 1) / ROWS_PER_THREAD;
    const int grid = (int)((nthreads + BLOCK - 1) / BLOCK);

    ffq_kernel<<<grid, BLOCK>>>(x, theta, w1, b1, w2, b2, out, nrows);
}

// round 4
// speedup vs baseline: 1.6356x; 1.6356x over previous
#include <cuda_runtime.h>

// out = relu(cos(x+theta) @ W1 + b1) @ W2 + b2
// x: [B*S, 8] fp32, W1: [8,32], W2: [32,8], out: [B*S, 8] fp32
//
// f32x2-packed (2 rows/lane, 2 pairs = 4 rows/thread). Layers fused in
// GROUPS of 4 hidden columns: 8 independent layer-1 FFMA2 chains (hides
// lat-4) while only h[4][2] is live (+16 regs vs full fusion).
// All shared weight loads are explicit ulonglong2 -> LDS.128.

using u64 = unsigned long long;

__device__ __forceinline__ u64 pack2(float lo, float hi) {
    u64 r;
    asm("mov.b64 %0, {%1, %2};" : "=l"(r) : "f"(lo), "f"(hi));
    return r;
}

__device__ __forceinline__ float2 unpack2(u64 v) {
    float2 f;
    asm("mov.b64 {%0, %1}, %2;" : "=f"(f.x), "=f"(f.y) : "l"(v));
    return f;
}

__device__ __forceinline__ u64 ffma2(u64 a, u64 b, u64 c) {
    u64 d;
    asm("fma.rn.f32x2 %0, %1, %2, %3;" : "=l"(d) : "l"(a), "l"(b), "l"(c));
    return d;
}

__device__ __forceinline__ u64 relu2(u64 v) {
    float2 f = unpack2(v);
    f.x = fmaxf(f.x, 0.0f);
    f.y = fmaxf(f.y, 0.0f);
    return pack2(f.x, f.y);
}

constexpr int E = 8;
constexpr int F = 32;
constexpr int JG = 4;                      // hidden columns per fused group
constexpr int PAIRS = 2;                   // f32x2 row-pairs per thread
constexpr int ROWS_PER_THREAD = 2 * PAIRS; // 4 rows/thread
constexpr int BLOCK = 128;

__global__ __launch_bounds__(BLOCK)
void ffq_kernel(const float* __restrict__ x,
                const float* __restrict__ theta,
                const float* __restrict__ w1,
                const float* __restrict__ b1,
                const float* __restrict__ w2,
                const float* __restrict__ b2,
                float* __restrict__ out,
                long nrows)
{
    // s_w1t[j*E + i] = {w1[i][j], w1[i][j]}  (column j contiguous, 16B-aligned)
    // s_w2 [j*E + e] = {w2[j][e], w2[j][e]}  (row j contiguous)
    __shared__ __align__(16) u64 s_w1t[F * E];
    __shared__ __align__(16) u64 s_w2 [F * E];
    __shared__ __align__(16) u64 s_b1 [F];
    __shared__ __align__(16) u64 s_b2 [E];
    __shared__ float s_th[E];

    const int t = threadIdx.x;

    for (int k = t; k < F * E; k += BLOCK) {
        int j = k / E, i = k % E;
        float a = w1[i * F + j];
        s_w1t[k] = pack2(a, a);
        float b = w2[k];                   // w2 is [F][E]; k = j*E+e
        s_w2[k] = pack2(b, b);
    }
    if (t < F) { float v = b1[t]; s_b1[t] = pack2(v, v); }
    if (t < E) {
        float v = b2[t]; s_b2[t] = pack2(v, v);
        s_th[t] = theta[t];
    }
    __syncthreads();

    const long row0 = ((long)blockIdx.x * BLOCK + t) * ROWS_PER_THREAD;
    if (row0 >= nrows) return;

    float th[E];
#pragma unroll
    for (int i = 0; i < E; i++) th[i] = s_th[i];

    // ---- Load x rows (8x LDG.128)
    const float4* xv = (const float4*)(x + row0 * E);
    float xr[ROWS_PER_THREAD][E];
#pragma unroll
    for (int r = 0; r < ROWS_PER_THREAD; r++) {
        float4 lo = xv[2 * r + 0];
        float4 hi = xv[2 * r + 1];
        xr[r][0] = lo.x; xr[r][1] = lo.y; xr[r][2] = lo.z; xr[r][3] = lo.w;
        xr[r][4] = hi.x; xr[r][5] = hi.y; xr[r][6] = hi.z; xr[r][7] = hi.w;
    }

    // ---- q = cos(x + theta), packed as {row 2p, row 2p+1}
    u64 q[PAIRS][E];
#pragma unroll
    for (int p = 0; p < PAIRS; p++) {
#pragma unroll
        for (int i = 0; i < E; i++) {
            float a = __cosf(xr[2 * p + 0][i] + th[i]);
            float b = __cosf(xr[2 * p + 1][i] + th[i]);
            q[p][i] = pack2(a, b);
        }
    }

    // ---- Fused in groups of JG=4 hidden columns
    u64 o[PAIRS][E];
#pragma unroll
    for (int e = 0; e < E; e++) {
        u64 be = s_b2[e];
        o[0][e] = be;
        o[1][e] = be;
    }

#pragma unroll
    for (int jg = 0; jg < F / JG; jg++) {
        const int j0 = jg * JG;

        // layer 1: h[jj][p], 8 independent chains
        u64 h[JG][PAIRS];
        {
            const ulonglong2* bb = (const ulonglong2*)&s_b1[j0];
#pragma unroll
            for (int jj2 = 0; jj2 < JG / 2; jj2++) {
                ulonglong2 b2v = bb[jj2];                 // LDS.128
                h[2 * jj2 + 0][0] = b2v.x; h[2 * jj2 + 0][1] = b2v.x;
                h[2 * jj2 + 1][0] = b2v.y; h[2 * jj2 + 1][1] = b2v.y;
            }
        }
#pragma unroll
        for (int jj = 0; jj < JG; jj++) {
            const ulonglong2* wc = (const ulonglong2*)&s_w1t[(j0 + jj) * E];
#pragma unroll
            for (int i2 = 0; i2 < E / 2; i2++) {
                ulonglong2 w = wc[i2];                    // LDS.128: 2 weights
                h[jj][0] = ffma2(q[0][2 * i2 + 0], w.x, h[jj][0]);
                h[jj][1] = ffma2(q[1][2 * i2 + 0], w.x, h[jj][1]);
                h[jj][0] = ffma2(q[0][2 * i2 + 1], w.y, h[jj][0]);
                h[jj][1] = ffma2(q[1][2 * i2 + 1], w.y, h[jj][1]);
            }
        }
#pragma unroll
        for (int jj = 0; jj < JG; jj++) {
            h[jj][0] = relu2(h[jj][0]);
            h[jj][1] = relu2(h[jj][1]);
        }

        // layer 2: accumulate into o (16 chains)
#pragma unroll
        for (int jj = 0; jj < JG; jj++) {
            const ulonglong2* wr = (const ulonglong2*)&s_w2[(j0 + jj) * E];
#pragma unroll
            for (int e2 = 0; e2 < E / 2; e2++) {
                ulonglong2 w = wr[e2];                    // LDS.128: 2 weights
                o[0][2 * e2 + 0] = ffma2(h[jj][0], w.x, o[0][2 * e2 + 0]);
                o[1][2 * e2 + 0] = ffma2(h[jj][1], w.x, o[1][2 * e2 + 0]);
                o[0][2 * e2 + 1] = ffma2(h[jj][0], w.y, o[0][2 * e2 + 1]);
                o[1][2 * e2 + 1] = ffma2(h[jj][1], w.y, o[1][2 * e2 + 1]);
            }
        }
    }

    // ---- Store 4 rows (8x STG.128): row 2p = lo halves, row 2p+1 = hi halves
    float4* ov = (float4*)(out + row0 * E);
#pragma unroll
    for (int p = 0; p < PAIRS; p++) {
        float2 f[E];
#pragma unroll
        for (int e = 0; e < E; e++) f[e] = unpack2(o[p][e]);
        ov[4 * p + 0] = make_float4(f[0].x, f[1].x, f[2].x, f[3].x);
        ov[4 * p + 1] = make_float4(f[4].x, f[5].x, f[6].x, f[7].x);
        ov[4 * p + 2] = make_float4(f[0].y, f[1].y, f[2].y, f[3].y);
        ov[4 * p + 3] = make_float4(f[4].y, f[5].y, f[6].y, f[7].y);
    }
}

extern "C" void kernel_launch(void* const* d_in, const int* in_sizes, int n_in,
                              void* d_out, int out_size)
{
    const float* x     = (const float*)d_in[0];
    const float* theta = (const float*)d_in[1];
    const float* w1    = (const float*)d_in[2];
    const float* b1    = (const float*)d_in[3];
    const float* w2    = (const float*)d_in[4];
    const float* b2    = (const float*)d_in[5];
    float* out = (float*)d_out;

    const long nrows = (long)in_sizes[0] / E;  // 524288
    const long nthreads = (nrows + ROWS_PER_THREAD - 1) / ROWS_PER_THREAD;
    const int grid = (int)((nthreads + BLOCK - 1) / BLOCK);

    ffq_kernel<<<grid, BLOCK>>>(x, theta, w1, b1, w2, b2, out, nrows);
}